// round 3
// baseline (speedup 1.0000x reference)
#include <cuda_runtime.h>
#include <math.h>

#define NC 3072
#define NT 1024
#define NTOK 4096
#define D 256
#define H 8
#define HD 32
#define FF 1024
#define L 2

// ---------------- scratch (static device allocations; allowed) ----------------
__device__ float g_c[NTOK * D];     // residual stream
__device__ float g_q[NTOK * D];
__device__ float g_k[NTOK * D];
__device__ float g_v[NTOK * D];
__device__ float g_o[NTOK * D];     // attention out / ffn2 out
__device__ float g_t[NTOK * FF];    // o-proj out (first 4096*256) / ffn hidden

// ---------------- decorator: c = [c_ctx;c_tgt] + (w*mask) * y_emb --------------
__global__ __launch_bounds__(256) void decorate_kernel(
    const float* __restrict__ c_ctx, const float* __restrict__ c_tgt,
    const float* __restrict__ y_ctx, const float* __restrict__ expo_ctx,
    const float* __restrict__ W1, const float* __restrict__ b1,
    const float* __restrict__ W2, const float* __restrict__ b2,
    const float* __restrict__ logk, float* __restrict__ c)
{
    const int row = blockIdx.x;
    const int j = threadIdx.x;
    if (row >= NC) {
        c[row * D + j] = c_tgt[(row - NC) * D + j];
        return;
    }
    __shared__ float t[D];
    const float y = y_ctx[row];
    t[j] = tanhf(y * W1[j] + b1[j]);
    __syncthreads();

    float acc = b2[j];
    #pragma unroll 8
    for (int d = 0; d < D; d++)
        acc += t[d] * W2[d * D + j];

    const float lk = logk[0];
    const float kappa = (lk > 20.f) ? lk : log1pf(expf(lk));   // softplus
    const float e = expo_ctx[row];
    const float w = e / (e + kappa);
    c[row * D + j] = c_ctx[row * D + j] + w * acc;
}

// ---------------- tiled SGEMM: C = A(MxK) @ B(KxN) + bias, optional relu ------
#define BM 64
#define BN 64
#define BK 16
__device__ __forceinline__ void sgemm_body(
    const float* __restrict__ A, const float* __restrict__ B,
    const float* __restrict__ bias, float* __restrict__ C,
    int N, int K, int relu)
{
    __shared__ float As[BK][BM + 4];
    __shared__ float Bs[BK][BN];

    const int tid = threadIdx.x;          // 256
    const int tx = tid & 15;              // 0..15
    const int ty = tid >> 4;              // 0..15
    const int bm = blockIdx.y * BM;
    const int bn = blockIdx.x * BN;

    const int arow = tid >> 2;            // 0..63
    const int acol = (tid & 3) << 2;      // 0,4,8,12
    const int brow = tid >> 4;            // 0..15
    const int bcol = (tid & 15) << 2;     // 0..60

    float acc[4][4] = {};

    for (int k0 = 0; k0 < K; k0 += BK) {
        float4 av = *(const float4*)&A[(bm + arow) * K + k0 + acol];
        As[acol + 0][arow] = av.x;
        As[acol + 1][arow] = av.y;
        As[acol + 2][arow] = av.z;
        As[acol + 3][arow] = av.w;
        *(float4*)&Bs[brow][bcol] = *(const float4*)&B[(k0 + brow) * N + bn + bcol];
        __syncthreads();

        #pragma unroll
        for (int kk = 0; kk < BK; kk++) {
            float a[4], b[4];
            *(float4*)a = *(const float4*)&As[kk][ty << 2];
            *(float4*)b = *(const float4*)&Bs[kk][tx << 2];
            #pragma unroll
            for (int i = 0; i < 4; i++)
                #pragma unroll
                for (int jj = 0; jj < 4; jj++)
                    acc[i][jj] += a[i] * b[jj];
        }
        __syncthreads();
    }

    #pragma unroll
    for (int i = 0; i < 4; i++) {
        const int row = bm + (ty << 2) + i;
        #pragma unroll
        for (int jj = 0; jj < 4; jj++) {
            const int col = bn + (tx << 2) + jj;
            float v = acc[i][jj] + bias[col];
            if (relu) v = fmaxf(v, 0.f);
            C[row * N + col] = v;
        }
    }
}

__global__ __launch_bounds__(256) void sgemm_bias(
    const float* __restrict__ A, const float* __restrict__ B,
    const float* __restrict__ bias, float* __restrict__ C,
    int N, int K, int relu)
{
    sgemm_body(A, B, bias, C, N, K, relu);
}

// Fused QKV: grid.z selects which projection (0=Q,1=K,2=V); one launch.
__global__ __launch_bounds__(256) void sgemm_qkv(
    const float* __restrict__ A,
    const float* __restrict__ WQ, const float* __restrict__ bQ, float* __restrict__ Q,
    const float* __restrict__ WK, const float* __restrict__ bK, float* __restrict__ K_,
    const float* __restrict__ WV, const float* __restrict__ bV, float* __restrict__ V)
{
    const float* B;  const float* bias;  float* C;
    if (blockIdx.z == 0)      { B = WQ; bias = bQ; C = Q;  }
    else if (blockIdx.z == 1) { B = WK; bias = bK; C = K_; }
    else                      { B = WV; bias = bV; C = V;  }
    sgemm_body(A, B, bias, C, D, D, 0);
}

// ---------------- attention: flash-style, 1 thread = 1 query row --------------
// Mask structure: only target-target (q!=k) pairs blocked. NC%64==0, so a
// 64-query tile is uniformly context or target. Context q: attend all 4096 keys.
// Target q: attend the 3072 context keys + itself (added from global at the end).
#define TQ 64
__global__ __launch_bounds__(64) void attn_kernel(
    const float* __restrict__ Q, const float* __restrict__ Kg,
    const float* __restrict__ Vg, float* __restrict__ O)
{
    const int h = blockIdx.y;
    const int qg = blockIdx.x * TQ + threadIdx.x;
    const int hc = h * HD;                 // head column offset

    __shared__ float Ks[TQ][HD + 4];
    __shared__ float Vs[TQ][HD + 4];

    float q[HD], acc[HD];
    #pragma unroll
    for (int i = 0; i < 8; i++) {
        float4 v = *(const float4*)&Q[qg * D + hc + i * 4];
        q[i*4+0] = v.x; q[i*4+1] = v.y; q[i*4+2] = v.z; q[i*4+3] = v.w;
        acc[i*4+0] = 0.f; acc[i*4+1] = 0.f; acc[i*4+2] = 0.f; acc[i*4+3] = 0.f;
    }
    float m = -INFINITY, l = 0.f;
    const bool tq = (qg >= NC);
    const int ntiles = tq ? (NC / TQ) : (NTOK / TQ);
    const float scale = 0.17677669529663687f;   // 1/sqrt(32)

    for (int kt = 0; kt < ntiles; kt++) {
        const int krow = kt * TQ + threadIdx.x;
        #pragma unroll
        for (int i = 0; i < 8; i++) {
            *(float4*)&Ks[threadIdx.x][i * 4] = *(const float4*)&Kg[krow * D + hc + i * 4];
            *(float4*)&Vs[threadIdx.x][i * 4] = *(const float4*)&Vg[krow * D + hc + i * 4];
        }
        __syncthreads();

        for (int k = 0; k < TQ; k++) {
            float s0 = 0.f, s1 = 0.f, s2 = 0.f, s3 = 0.f;
            #pragma unroll
            for (int i = 0; i < 8; i++) {
                float4 kv = *(const float4*)&Ks[k][i * 4];
                s0 += q[i*4+0] * kv.x;
                s1 += q[i*4+1] * kv.y;
                s2 += q[i*4+2] * kv.z;
                s3 += q[i*4+3] * kv.w;
            }
            float s = (s0 + s1 + s2 + s3) * scale;
            if (s > m) {
                const float corr = __expf(m - s);
                m = s;
                l = l * corr + 1.f;
                #pragma unroll
                for (int i = 0; i < 8; i++) {
                    float4 vv = *(const float4*)&Vs[k][i * 4];
                    acc[i*4+0] = acc[i*4+0] * corr + vv.x;
                    acc[i*4+1] = acc[i*4+1] * corr + vv.y;
                    acc[i*4+2] = acc[i*4+2] * corr + vv.z;
                    acc[i*4+3] = acc[i*4+3] * corr + vv.w;
                }
            } else {
                const float p = __expf(s - m);
                l += p;
                #pragma unroll
                for (int i = 0; i < 8; i++) {
                    float4 vv = *(const float4*)&Vs[k][i * 4];
                    acc[i*4+0] += p * vv.x;
                    acc[i*4+1] += p * vv.y;
                    acc[i*4+2] += p * vv.z;
                    acc[i*4+3] += p * vv.w;
                }
            }
        }
        __syncthreads();
    }

    if (tq) {   // self term for target queries
        float s = 0.f;
        #pragma unroll
        for (int i = 0; i < 8; i++) {
            float4 kv = *(const float4*)&Kg[qg * D + hc + i * 4];
            s += q[i*4+0]*kv.x + q[i*4+1]*kv.y + q[i*4+2]*kv.z + q[i*4+3]*kv.w;
        }
        s *= scale;
        if (s > m) {
            const float corr = __expf(m - s);
            m = s; l = l * corr + 1.f;
            #pragma unroll
            for (int i = 0; i < 8; i++) {
                float4 vv = *(const float4*)&Vg[qg * D + hc + i * 4];
                acc[i*4+0] = acc[i*4+0] * corr + vv.x;
                acc[i*4+1] = acc[i*4+1] * corr + vv.y;
                acc[i*4+2] = acc[i*4+2] * corr + vv.z;
                acc[i*4+3] = acc[i*4+3] * corr + vv.w;
            }
        } else {
            const float p = __expf(s - m);
            l += p;
            #pragma unroll
            for (int i = 0; i < 8; i++) {
                float4 vv = *(const float4*)&Vg[qg * D + hc + i * 4];
                acc[i*4+0] += p * vv.x;
                acc[i*4+1] += p * vv.y;
                acc[i*4+2] += p * vv.z;
                acc[i*4+3] += p * vv.w;
            }
        }
    }

    const float inv = 1.f / l;
    #pragma unroll
    for (int i = 0; i < 8; i++) {
        float4 o;
        o.x = acc[i*4+0] * inv; o.y = acc[i*4+1] * inv;
        o.z = acc[i*4+2] * inv; o.w = acc[i*4+3] * inv;
        *(float4*)&O[qg * D + hc + i * 4] = o;
    }
}

// ---------------- fused residual add + LayerNorm: c = LN(c + t) ---------------
// 256 threads = 8 warps. Race-free: separate smem arrays for sum and sumsq,
// single barrier before the warp-0 combine.
__global__ __launch_bounds__(256) void add_ln_kernel(
    float* __restrict__ c, const float* __restrict__ t,
    const float* __restrict__ g, const float* __restrict__ b)
{
    const int row = blockIdx.x;
    const int j = threadIdx.x;
    const int lane = j & 31, warp = j >> 5;
    __shared__ float wsum[8], wsq[8];
    __shared__ float s_mean, s_rstd;

    float x = c[row * D + j] + t[row * D + j];

    float s1 = x, s2 = x * x;
    #pragma unroll
    for (int o = 16; o > 0; o >>= 1) {
        s1 += __shfl_xor_sync(0xffffffffu, s1, o);
        s2 += __shfl_xor_sync(0xffffffffu, s2, o);
    }
    if (lane == 0) { wsum[warp] = s1; wsq[warp] = s2; }
    __syncthreads();
    if (warp == 0) {
        float v1 = (lane < 8) ? wsum[lane] : 0.f;
        float v2 = (lane < 8) ? wsq[lane] : 0.f;
        #pragma unroll
        for (int o = 4; o > 0; o >>= 1) {
            v1 += __shfl_xor_sync(0xffffffffu, v1, o);
            v2 += __shfl_xor_sync(0xffffffffu, v2, o);
        }
        if (lane == 0) {
            const float mean = v1 * (1.0f / D);
            float var = v2 * (1.0f / D) - mean * mean;
            var = fmaxf(var, 0.f);
            s_mean = mean;
            s_rstd = rsqrtf(var + 1e-5f);
        }
    }
    __syncthreads();
    c[row * D + j] = (x - s_mean) * s_rstd * g[j] + b[j];
}

// ---------------- output head: out = exp(c[NC:] @ W + b) * exposure ----------
__global__ __launch_bounds__(256) void out_kernel(
    const float* __restrict__ c, const float* __restrict__ W,
    const float* __restrict__ ob, const float* __restrict__ expo,
    float* __restrict__ out)
{
    const int i = blockIdx.x;
    const int j = threadIdx.x;
    const int lane = j & 31, warp = j >> 5;
    __shared__ float wred[8];
    float s = c[(NC + i) * D + j] * W[j];
    #pragma unroll
    for (int o = 16; o > 0; o >>= 1) s += __shfl_xor_sync(0xffffffffu, s, o);
    if (lane == 0) wred[warp] = s;
    __syncthreads();
    if (j == 0) {
        float v = wred[0];
        #pragma unroll
        for (int w = 1; w < 8; w++) v += wred[w];
        out[i] = expf(v + ob[0]) * expo[i];
    }
}

// ---------------- launch ----------------
extern "C" void kernel_launch(void* const* d_in, const int* in_sizes, int n_in,
                              void* d_out, int out_size)
{
    const float* c_ctx    = (const float*)d_in[0];
    const float* c_tgt    = (const float*)d_in[1];
    const float* y_ctx    = (const float*)d_in[2];
    const float* expo_ctx = (const float*)d_in[3];
    const float* expo_tgt = (const float*)d_in[4];
    const float* dec_W1   = (const float*)d_in[5];
    const float* dec_b1   = (const float*)d_in[6];
    const float* dec_W2   = (const float*)d_in[7];
    const float* dec_b2   = (const float*)d_in[8];
    const float* log_k    = (const float*)d_in[9];
    const float* WQ       = (const float*)d_in[10];
    const float* bQ       = (const float*)d_in[11];
    const float* WK       = (const float*)d_in[12];
    const float* bK       = (const float*)d_in[13];
    const float* WV       = (const float*)d_in[14];
    const float* bV       = (const float*)d_in[15];
    const float* WO       = (const float*)d_in[16];
    const float* bO       = (const float*)d_in[17];
    const float* ln1_g    = (const float*)d_in[18];
    const float* ln1_b    = (const float*)d_in[19];
    const float* ln2_g    = (const float*)d_in[20];
    const float* ln2_b    = (const float*)d_in[21];
    const float* ffn_W1   = (const float*)d_in[22];
    const float* ffn_b1   = (const float*)d_in[23];
    const float* ffn_W2   = (const float*)d_in[24];
    const float* ffn_b2   = (const float*)d_in[25];
    const float* out_W    = (const float*)d_in[26];
    const float* out_b    = (const float*)d_in[27];
    float* out = (float*)d_out;

    float *pc, *pq, *pk, *pv, *po, *pt;
    cudaGetSymbolAddress((void**)&pc, g_c);
    cudaGetSymbolAddress((void**)&pq, g_q);
    cudaGetSymbolAddress((void**)&pk, g_k);
    cudaGetSymbolAddress((void**)&pv, g_v);
    cudaGetSymbolAddress((void**)&po, g_o);
    cudaGetSymbolAddress((void**)&pt, g_t);

    decorate_kernel<<<NTOK, 256>>>(c_ctx, c_tgt, y_ctx, expo_ctx,
                                   dec_W1, dec_b1, dec_W2, dec_b2, log_k, pc);

    const dim3 gD(D / BN, NTOK / BM);          // 4 x 64
    const dim3 gQKV(D / BN, NTOK / BM, 3);     // 4 x 64 x 3
    const dim3 gFF1(FF / BN, NTOK / BM);       // 16 x 64

    for (int l = 0; l < L; l++) {
        sgemm_qkv<<<gQKV, 256>>>(pc,
            WQ + l * D * D, bQ + l * D, pq,
            WK + l * D * D, bK + l * D, pk,
            WV + l * D * D, bV + l * D, pv);

        attn_kernel<<<dim3(NTOK / TQ, H), TQ>>>(pq, pk, pv, po);

        sgemm_bias<<<gD, 256>>>(po, WO + l * D * D, bO + l * D, pt, D, D, 0);
        add_ln_kernel<<<NTOK, 256>>>(pc, pt, ln1_g + l * D, ln1_b + l * D);

        sgemm_bias<<<gFF1, 256>>>(pc, ffn_W1 + l * D * FF, ffn_b1 + l * FF, pt,
                                  FF, D, 1);
        sgemm_bias<<<gD, 256>>>(pt, ffn_W2 + l * FF * D, ffn_b2 + l * D, po,
                                D, FF, 0);
        add_ln_kernel<<<NTOK, 256>>>(pc, po, ln2_g + l * D, ln2_b + l * D);
    }

    out_kernel<<<NT, 256>>>(pc, out_W, out_b, expo_tgt, out);
}

// round 4
// speedup vs baseline: 3.9617x; 3.9617x over previous
#include <cuda_runtime.h>
#include <cuda_bf16.h>
#include <math.h>

#define NC 3072
#define NT 1024
#define NTOK 4096
#define D 256
#define H 8
#define HD 32
#define FF 1024
#define L 2

// ---------------- scratch ----------------
__device__ float g_c[NTOK * D];
__device__ float g_q[NTOK * D];
__device__ float g_k[NTOK * D];
__device__ float g_v[NTOK * D];
__device__ float g_o[NTOK * D];
__device__ float g_t[NTOK * FF];

// ---------------- mma helpers ----------------
__device__ __forceinline__ unsigned f2tf32(float x) {
    unsigned r; asm("cvt.rna.tf32.f32 %0, %1;" : "=r"(r) : "f"(x)); return r;
}
__device__ __forceinline__ unsigned pack_bf16(float x, float y) {
    __nv_bfloat162 h = __floats2bfloat162_rn(x, y);   // .x = low half = x
    return *(unsigned*)&h;
}
__device__ __forceinline__ void mma_tf32(float* d, const unsigned* a, const unsigned* b) {
    asm volatile("mma.sync.aligned.m16n8k8.row.col.f32.tf32.tf32.f32 "
        "{%0,%1,%2,%3}, {%4,%5,%6,%7}, {%8,%9}, {%0,%1,%2,%3};"
        : "+f"(d[0]), "+f"(d[1]), "+f"(d[2]), "+f"(d[3])
        : "r"(a[0]), "r"(a[1]), "r"(a[2]), "r"(a[3]), "r"(b[0]), "r"(b[1]));
}
__device__ __forceinline__ void mma_bf16(float* d, const unsigned* a, const unsigned* b) {
    asm volatile("mma.sync.aligned.m16n8k16.row.col.f32.bf16.bf16.f32 "
        "{%0,%1,%2,%3}, {%4,%5,%6,%7}, {%8,%9}, {%0,%1,%2,%3};"
        : "+f"(d[0]), "+f"(d[1]), "+f"(d[2]), "+f"(d[3])
        : "r"(a[0]), "r"(a[1]), "r"(a[2]), "r"(a[3]), "r"(b[0]), "r"(b[1]));
}

// ---------------- decorator ----------------
__global__ __launch_bounds__(256) void decorate_kernel(
    const float* __restrict__ c_ctx, const float* __restrict__ c_tgt,
    const float* __restrict__ y_ctx, const float* __restrict__ expo_ctx,
    const float* __restrict__ W1, const float* __restrict__ b1,
    const float* __restrict__ W2, const float* __restrict__ b2,
    const float* __restrict__ logk, float* __restrict__ c)
{
    const int row = blockIdx.x;
    const int j = threadIdx.x;
    if (row >= NC) {
        c[row * D + j] = c_tgt[(row - NC) * D + j];
        return;
    }
    __shared__ float t[D];
    const float y = y_ctx[row];
    t[j] = tanhf(y * W1[j] + b1[j]);
    __syncthreads();

    float acc = b2[j];
    #pragma unroll 8
    for (int d = 0; d < D; d++)
        acc += t[d] * W2[d * D + j];

    const float lk = logk[0];
    const float kappa = (lk > 20.f) ? lk : log1pf(expf(lk));
    const float e = expo_ctx[row];
    const float w = e / (e + kappa);
    c[row * D + j] = c_ctx[row * D + j] + w * acc;
}

// ---------------- tf32 tensor-core GEMM: C = A(MxK)@B(KxN) + bias [,relu] ----
// block tile 128x64, 256 thr = 8 warps in 4x2, warp tile 32x32 (2 m16 x 4 n8)
#define GBM 128
#define GBN 64
#define GBK 32
__device__ __forceinline__ void gemm_tf32_body(
    const float* __restrict__ A, const float* __restrict__ B,
    const float* __restrict__ bias, float* __restrict__ C,
    int N, int K, int relu)
{
    __shared__ float As[GBK][GBM + 8];   // [k][m]
    __shared__ float Bs[GBK][GBN + 8];   // [k][n]

    const int tid = threadIdx.x;
    const int lane = tid & 31, warp = tid >> 5;
    const int wm = warp >> 1, wn = warp & 1;
    const int bm = blockIdx.y * GBM, bn = blockIdx.x * GBN;
    const int lq = lane >> 2, lr = lane & 3;      // groupID, tid-in-group

    float acc[2][4][4] = {};

    const int arow = tid >> 1, ak = (tid & 1) * 16;
    const int bk = tid >> 3, bn4 = (tid & 7) * 8;

    for (int k0 = 0; k0 < K; k0 += GBK) {
        #pragma unroll
        for (int j = 0; j < 16; j += 4) {
            float4 v = *(const float4*)&A[(bm + arow) * K + k0 + ak + j];
            As[ak + j + 0][arow] = __uint_as_float(f2tf32(v.x));
            As[ak + j + 1][arow] = __uint_as_float(f2tf32(v.y));
            As[ak + j + 2][arow] = __uint_as_float(f2tf32(v.z));
            As[ak + j + 3][arow] = __uint_as_float(f2tf32(v.w));
        }
        #pragma unroll
        for (int j = 0; j < 8; j += 4) {
            float4 v = *(const float4*)&B[(k0 + bk) * N + bn + bn4 + j];
            Bs[bk][bn4 + j + 0] = __uint_as_float(f2tf32(v.x));
            Bs[bk][bn4 + j + 1] = __uint_as_float(f2tf32(v.y));
            Bs[bk][bn4 + j + 2] = __uint_as_float(f2tf32(v.z));
            Bs[bk][bn4 + j + 3] = __uint_as_float(f2tf32(v.w));
        }
        __syncthreads();

        #pragma unroll
        for (int kz = 0; kz < GBK; kz += 8) {
            unsigned af[2][4], bf[4][2];
            #pragma unroll
            for (int mt = 0; mt < 2; mt++) {
                const int mr = wm * 32 + mt * 16 + lq;
                af[mt][0] = __float_as_uint(As[kz + lr][mr]);        // (r,   c)
                af[mt][1] = __float_as_uint(As[kz + lr][mr + 8]);    // (r+8, c)
                af[mt][2] = __float_as_uint(As[kz + lr + 4][mr]);    // (r,   c+4)
                af[mt][3] = __float_as_uint(As[kz + lr + 4][mr + 8]);// (r+8, c+4)
            }
            #pragma unroll
            for (int nt = 0; nt < 4; nt++) {
                const int nc0 = wn * 32 + nt * 8 + lq;
                bf[nt][0] = __float_as_uint(Bs[kz + lr][nc0]);
                bf[nt][1] = __float_as_uint(Bs[kz + lr + 4][nc0]);
            }
            #pragma unroll
            for (int mt = 0; mt < 2; mt++)
                #pragma unroll
                for (int nt = 0; nt < 4; nt++)
                    mma_tf32(acc[mt][nt], af[mt], bf[nt]);
        }
        __syncthreads();
    }

    #pragma unroll
    for (int mt = 0; mt < 2; mt++) {
        const int row = bm + wm * 32 + mt * 16 + lq;
        #pragma unroll
        for (int nt = 0; nt < 4; nt++) {
            const int col = bn + wn * 32 + nt * 8 + lr * 2;
            const float b0 = bias[col], b1 = bias[col + 1];
            float v0 = acc[mt][nt][0] + b0, v1 = acc[mt][nt][1] + b1;
            float v2 = acc[mt][nt][2] + b0, v3 = acc[mt][nt][3] + b1;
            if (relu) {
                v0 = fmaxf(v0, 0.f); v1 = fmaxf(v1, 0.f);
                v2 = fmaxf(v2, 0.f); v3 = fmaxf(v3, 0.f);
            }
            *(float2*)&C[row * N + col] = make_float2(v0, v1);
            *(float2*)&C[(row + 8) * N + col] = make_float2(v2, v3);
        }
    }
}

__global__ __launch_bounds__(256) void gemm_tf32_kernel(
    const float* __restrict__ A, const float* __restrict__ B,
    const float* __restrict__ bias, float* __restrict__ C,
    int N, int K, int relu)
{
    gemm_tf32_body(A, B, bias, C, N, K, relu);
}

__global__ __launch_bounds__(256) void gemm_qkv_kernel(
    const float* __restrict__ A,
    const float* __restrict__ WQ, const float* __restrict__ bQ, float* __restrict__ Q,
    const float* __restrict__ WK, const float* __restrict__ bK, float* __restrict__ K_,
    const float* __restrict__ WV, const float* __restrict__ bV, float* __restrict__ V)
{
    const float* B; const float* bias; float* C;
    if (blockIdx.z == 0)      { B = WQ; bias = bQ; C = Q;  }
    else if (blockIdx.z == 1) { B = WK; bias = bK; C = K_; }
    else                      { B = WV; bias = bV; C = V;  }
    gemm_tf32_body(A, B, bias, C, D, D, 0);
}

// ---------------- bf16 tensor-core flash attention -------------------------
// Block: 64 queries x 1 head, 128 threads (4 warps x 16 queries).
// K tile [64 keys x 32 d] bf16, V tile transposed [32 d x 64 keys] bf16.
// Target q-blocks (blockIdx.x >= 48) loop only the 48 context k-tiles, then
// add the fp32 self-term.
#define AQ 64
#define AK 64
__global__ __launch_bounds__(128) void attn_mma_kernel(
    const float* __restrict__ Qg, const float* __restrict__ Kg,
    const float* __restrict__ Vg, float* __restrict__ Og)
{
    __shared__ __nv_bfloat16 Ks[AK][40];    // [key][d], pad 8 halves
    __shared__ __nv_bfloat16 Vts[HD][72];   // [d][key], pad 8 halves

    const int hc = blockIdx.y * HD;
    const int qb = blockIdx.x * AQ;
    const int tid = threadIdx.x, lane = tid & 31, warp = tid >> 5;
    const int lq = lane >> 2, lr = lane & 3;
    const int qw = qb + warp * 16;
    const bool tgt = (qb >= NC);
    const int ntiles = tgt ? (NC / AK) : (NTOK / AK);
    const float scale = 0.17677669529663687f;   // 1/sqrt(32)

    // Q fragments (persist across k-tiles): qa[kc] covers d-chunk kc*16..+15
    unsigned qa[2][4];
    {
        const int r0 = qw + lq;
        #pragma unroll
        for (int kc = 0; kc < 2; kc++) {
            const int d = hc + kc * 16 + lr * 2;
            float2 v00 = *(const float2*)&Qg[r0 * D + d];
            float2 v10 = *(const float2*)&Qg[(r0 + 8) * D + d];
            float2 v01 = *(const float2*)&Qg[r0 * D + d + 8];
            float2 v11 = *(const float2*)&Qg[(r0 + 8) * D + d + 8];
            qa[kc][0] = pack_bf16(v00.x, v00.y);
            qa[kc][1] = pack_bf16(v10.x, v10.y);
            qa[kc][2] = pack_bf16(v01.x, v01.y);
            qa[kc][3] = pack_bf16(v11.x, v11.y);
        }
    }

    float o[4][4] = {};
    float mrow[2] = { -INFINITY, -INFINITY };
    float lrow[2] = { 0.f, 0.f };

    for (int kt = 0; kt < ntiles; kt++) {
        const int kr = kt * AK;
        __syncthreads();
        {   // load K, V tiles (fp32 gmem -> bf16 smem; V transposed)
            const int key = tid >> 1, db = (tid & 1) * 16;
            const float* ksrc = &Kg[(kr + key) * D + hc + db];
            #pragma unroll
            for (int j = 0; j < 16; j += 4) {
                float4 v = *(const float4*)&ksrc[j];
                *(__nv_bfloat162*)&Ks[key][db + j]     = __floats2bfloat162_rn(v.x, v.y);
                *(__nv_bfloat162*)&Ks[key][db + j + 2] = __floats2bfloat162_rn(v.z, v.w);
            }
            const float* vsrc = &Vg[(kr + key) * D + hc + db];
            #pragma unroll
            for (int j = 0; j < 16; j += 4) {
                float4 v = *(const float4*)&vsrc[j];
                Vts[db + j + 0][key] = __float2bfloat16(v.x);
                Vts[db + j + 1][key] = __float2bfloat16(v.y);
                Vts[db + j + 2][key] = __float2bfloat16(v.z);
                Vts[db + j + 3][key] = __float2bfloat16(v.w);
            }
        }
        __syncthreads();

        // S = Q @ K^T : 8 n-tiles (8 keys each) x 2 d-chunks
        float s[8][4] = {};
        #pragma unroll
        for (int nt = 0; nt < 8; nt++) {
            #pragma unroll
            for (int kc = 0; kc < 2; kc++) {
                unsigned bfr[2];
                bfr[0] = *(const unsigned*)&Ks[nt * 8 + lq][kc * 16 + lr * 2];
                bfr[1] = *(const unsigned*)&Ks[nt * 8 + lq][kc * 16 + lr * 2 + 8];
                mma_bf16(s[nt], qa[kc], bfr);
            }
        }

        // online softmax on fragments (rows r0 = lane>>2, r1 = r0+8)
        float mt0 = -INFINITY, mt1 = -INFINITY;
        #pragma unroll
        for (int nt = 0; nt < 8; nt++) {
            s[nt][0] *= scale; s[nt][1] *= scale;
            s[nt][2] *= scale; s[nt][3] *= scale;
            mt0 = fmaxf(mt0, fmaxf(s[nt][0], s[nt][1]));
            mt1 = fmaxf(mt1, fmaxf(s[nt][2], s[nt][3]));
        }
        mt0 = fmaxf(mt0, __shfl_xor_sync(0xffffffffu, mt0, 1));
        mt0 = fmaxf(mt0, __shfl_xor_sync(0xffffffffu, mt0, 2));
        mt1 = fmaxf(mt1, __shfl_xor_sync(0xffffffffu, mt1, 1));
        mt1 = fmaxf(mt1, __shfl_xor_sync(0xffffffffu, mt1, 2));

        const float mn0 = fmaxf(mrow[0], mt0), mn1 = fmaxf(mrow[1], mt1);
        const float cr0 = __expf(mrow[0] - mn0), cr1 = __expf(mrow[1] - mn1);
        float rs0 = 0.f, rs1 = 0.f;
        #pragma unroll
        for (int nt = 0; nt < 8; nt++) {
            s[nt][0] = __expf(s[nt][0] - mn0);
            s[nt][1] = __expf(s[nt][1] - mn0);
            s[nt][2] = __expf(s[nt][2] - mn1);
            s[nt][3] = __expf(s[nt][3] - mn1);
            rs0 += s[nt][0] + s[nt][1];
            rs1 += s[nt][2] + s[nt][3];
        }
        rs0 += __shfl_xor_sync(0xffffffffu, rs0, 1);
        rs0 += __shfl_xor_sync(0xffffffffu, rs0, 2);
        rs1 += __shfl_xor_sync(0xffffffffu, rs1, 1);
        rs1 += __shfl_xor_sync(0xffffffffu, rs1, 2);
        lrow[0] = lrow[0] * cr0 + rs0;
        lrow[1] = lrow[1] * cr1 + rs1;
        mrow[0] = mn0; mrow[1] = mn1;
        #pragma unroll
        for (int nt = 0; nt < 4; nt++) {
            o[nt][0] *= cr0; o[nt][1] *= cr0;
            o[nt][2] *= cr1; o[nt][3] *= cr1;
        }

        // O += P @ V : 4 key-chunks (16 keys) x 4 d-tiles (8 each)
        #pragma unroll
        for (int kc = 0; kc < 4; kc++) {
            unsigned pa[4];
            pa[0] = pack_bf16(s[2 * kc][0],     s[2 * kc][1]);
            pa[1] = pack_bf16(s[2 * kc][2],     s[2 * kc][3]);
            pa[2] = pack_bf16(s[2 * kc + 1][0], s[2 * kc + 1][1]);
            pa[3] = pack_bf16(s[2 * kc + 1][2], s[2 * kc + 1][3]);
            #pragma unroll
            for (int nt = 0; nt < 4; nt++) {
                unsigned bfr[2];
                bfr[0] = *(const unsigned*)&Vts[nt * 8 + lq][kc * 16 + lr * 2];
                bfr[1] = *(const unsigned*)&Vts[nt * 8 + lq][kc * 16 + lr * 2 + 8];
                mma_bf16(o[nt], pa, bfr);
            }
        }
    }

    if (tgt) {   // fp32 self term for target queries
        #pragma unroll
        for (int rr = 0; rr < 2; rr++) {
            const int q = qw + lq + rr * 8;
            float sv = 0.f;
            #pragma unroll
            for (int d = 0; d < HD; d++)
                sv += Qg[q * D + hc + d] * Kg[q * D + hc + d];
            sv *= scale;
            const float mn = fmaxf(mrow[rr], sv);
            const float corr = __expf(mrow[rr] - mn);
            const float p = __expf(sv - mn);
            #pragma unroll
            for (int nt = 0; nt < 4; nt++) {
                const int dcol = hc + nt * 8 + lr * 2;
                o[nt][rr * 2 + 0] = o[nt][rr * 2 + 0] * corr + p * Vg[q * D + dcol];
                o[nt][rr * 2 + 1] = o[nt][rr * 2 + 1] * corr + p * Vg[q * D + dcol + 1];
            }
            lrow[rr] = lrow[rr] * corr + p;
            mrow[rr] = mn;
        }
    }

    const float inv0 = 1.f / lrow[0], inv1 = 1.f / lrow[1];
    const int r0 = qw + lq;
    #pragma unroll
    for (int nt = 0; nt < 4; nt++) {
        const int dcol = hc + nt * 8 + lr * 2;
        *(float2*)&Og[r0 * D + dcol] = make_float2(o[nt][0] * inv0, o[nt][1] * inv0);
        *(float2*)&Og[(r0 + 8) * D + dcol] = make_float2(o[nt][2] * inv1, o[nt][3] * inv1);
    }
}

// ---------------- fused residual add + LayerNorm ---------------------------
__global__ __launch_bounds__(256) void add_ln_kernel(
    float* __restrict__ c, const float* __restrict__ t,
    const float* __restrict__ g, const float* __restrict__ b)
{
    const int row = blockIdx.x;
    const int j = threadIdx.x;
    const int lane = j & 31, warp = j >> 5;
    __shared__ float wsum[8], wsq[8];
    __shared__ float s_mean, s_rstd;

    float x = c[row * D + j] + t[row * D + j];

    float s1 = x, s2 = x * x;
    #pragma unroll
    for (int o = 16; o > 0; o >>= 1) {
        s1 += __shfl_xor_sync(0xffffffffu, s1, o);
        s2 += __shfl_xor_sync(0xffffffffu, s2, o);
    }
    if (lane == 0) { wsum[warp] = s1; wsq[warp] = s2; }
    __syncthreads();
    if (warp == 0) {
        float v1 = (lane < 8) ? wsum[lane] : 0.f;
        float v2 = (lane < 8) ? wsq[lane] : 0.f;
        #pragma unroll
        for (int o = 4; o > 0; o >>= 1) {
            v1 += __shfl_xor_sync(0xffffffffu, v1, o);
            v2 += __shfl_xor_sync(0xffffffffu, v2, o);
        }
        if (lane == 0) {
            const float mean = v1 * (1.0f / D);
            float var = v2 * (1.0f / D) - mean * mean;
            var = fmaxf(var, 0.f);
            s_mean = mean;
            s_rstd = rsqrtf(var + 1e-5f);
        }
    }
    __syncthreads();
    c[row * D + j] = (x - s_mean) * s_rstd * g[j] + b[j];
}

// ---------------- output head ----------------------------------------------
__global__ __launch_bounds__(256) void out_kernel(
    const float* __restrict__ c, const float* __restrict__ W,
    const float* __restrict__ ob, const float* __restrict__ expo,
    float* __restrict__ out)
{
    const int i = blockIdx.x;
    const int j = threadIdx.x;
    const int lane = j & 31, warp = j >> 5;
    __shared__ float wred[8];
    float s = c[(NC + i) * D + j] * W[j];
    #pragma unroll
    for (int o = 16; o > 0; o >>= 1) s += __shfl_xor_sync(0xffffffffu, s, o);
    if (lane == 0) wred[warp] = s;
    __syncthreads();
    if (j == 0) {
        float v = wred[0];
        #pragma unroll
        for (int w = 1; w < 8; w++) v += wred[w];
        out[i] = expf(v + ob[0]) * expo[i];
    }
}

// ---------------- launch ----------------
extern "C" void kernel_launch(void* const* d_in, const int* in_sizes, int n_in,
                              void* d_out, int out_size)
{
    const float* c_ctx    = (const float*)d_in[0];
    const float* c_tgt    = (const float*)d_in[1];
    const float* y_ctx    = (const float*)d_in[2];
    const float* expo_ctx = (const float*)d_in[3];
    const float* expo_tgt = (const float*)d_in[4];
    const float* dec_W1   = (const float*)d_in[5];
    const float* dec_b1   = (const float*)d_in[6];
    const float* dec_W2   = (const float*)d_in[7];
    const float* dec_b2   = (const float*)d_in[8];
    const float* log_k    = (const float*)d_in[9];
    const float* WQ       = (const float*)d_in[10];
    const float* bQ       = (const float*)d_in[11];
    const float* WK       = (const float*)d_in[12];
    const float* bK       = (const float*)d_in[13];
    const float* WV       = (const float*)d_in[14];
    const float* bV       = (const float*)d_in[15];
    const float* WO       = (const float*)d_in[16];
    const float* bO       = (const float*)d_in[17];
    const float* ln1_g    = (const float*)d_in[18];
    const float* ln1_b    = (const float*)d_in[19];
    const float* ln2_g    = (const float*)d_in[20];
    const float* ln2_b    = (const float*)d_in[21];
    const float* ffn_W1   = (const float*)d_in[22];
    const float* ffn_b1   = (const float*)d_in[23];
    const float* ffn_W2   = (const float*)d_in[24];
    const float* ffn_b2   = (const float*)d_in[25];
    const float* out_W    = (const float*)d_in[26];
    const float* out_b    = (const float*)d_in[27];
    float* out = (float*)d_out;

    float *pc, *pq, *pk, *pv, *po, *pt;
    cudaGetSymbolAddress((void**)&pc, g_c);
    cudaGetSymbolAddress((void**)&pq, g_q);
    cudaGetSymbolAddress((void**)&pk, g_k);
    cudaGetSymbolAddress((void**)&pv, g_v);
    cudaGetSymbolAddress((void**)&po, g_o);
    cudaGetSymbolAddress((void**)&pt, g_t);

    decorate_kernel<<<NTOK, 256>>>(c_ctx, c_tgt, y_ctx, expo_ctx,
                                   dec_W1, dec_b1, dec_W2, dec_b2, log_k, pc);

    const dim3 gD(D / GBN, NTOK / GBM);          // 4 x 32
    const dim3 gQKV(D / GBN, NTOK / GBM, 3);     // 4 x 32 x 3
    const dim3 gFF1(FF / GBN, NTOK / GBM);       // 16 x 32
    const dim3 gAttn(NTOK / AQ, H);              // 64 x 8

    for (int l = 0; l < L; l++) {
        gemm_qkv_kernel<<<gQKV, 256>>>(pc,
            WQ + l * D * D, bQ + l * D, pq,
            WK + l * D * D, bK + l * D, pk,
            WV + l * D * D, bV + l * D, pv);

        attn_mma_kernel<<<gAttn, 128>>>(pq, pk, pv, po);

        gemm_tf32_kernel<<<gD, 256>>>(po, WO + l * D * D, bO + l * D, pt, D, D, 0);
        add_ln_kernel<<<NTOK, 256>>>(pc, pt, ln1_g + l * D, ln1_b + l * D);

        gemm_tf32_kernel<<<gFF1, 256>>>(pc, ffn_W1 + l * D * FF, ffn_b1 + l * FF,
                                        pt, FF, D, 1);
        gemm_tf32_kernel<<<gD, 256>>>(pt, ffn_W2 + l * FF * D, ffn_b2 + l * D,
                                      po, D, FF, 0);
        add_ln_kernel<<<NTOK, 256>>>(pc, po, ln2_g + l * D, ln2_b + l * D);
    }

    out_kernel<<<NT, 256>>>(pc, out_W, out_b, expo_tgt, out);
}

// round 5
// speedup vs baseline: 6.0724x; 1.5328x over previous
#include <cuda_runtime.h>
#include <cuda_bf16.h>
#include <math.h>

#define NC 3072
#define NT 1024
#define NTOK 4096
#define D 256
#define H 8
#define HD 32
#define FF 1024
#define L 2

// ---------------- scratch ----------------
__device__ float g_c[NTOK * D];
__device__ float g_q[NTOK * D];
__device__ float g_k[NTOK * D];
__device__ float g_v[NTOK * D];
__device__ float g_o[NTOK * D];
__device__ float g_t[NTOK * FF];
__device__ __nv_bfloat16 g_kb[NTOK * D];   // bf16 K
__device__ __nv_bfloat16 g_vt[D * NTOK];   // bf16 V^T  [d][token]

// ---------------- helpers ----------------
__device__ __forceinline__ unsigned f2tf32(float x) {
    unsigned r; asm("cvt.rna.tf32.f32 %0, %1;" : "=r"(r) : "f"(x)); return r;
}
__device__ __forceinline__ unsigned pack_bf16(float x, float y) {
    __nv_bfloat162 h = __floats2bfloat162_rn(x, y);
    return *(unsigned*)&h;
}
__device__ __forceinline__ void mma_tf32(float* d, const unsigned* a, const unsigned* b) {
    asm volatile("mma.sync.aligned.m16n8k8.row.col.f32.tf32.tf32.f32 "
        "{%0,%1,%2,%3}, {%4,%5,%6,%7}, {%8,%9}, {%0,%1,%2,%3};"
        : "+f"(d[0]), "+f"(d[1]), "+f"(d[2]), "+f"(d[3])
        : "r"(a[0]), "r"(a[1]), "r"(a[2]), "r"(a[3]), "r"(b[0]), "r"(b[1]));
}
__device__ __forceinline__ void mma_bf16(float* d, const unsigned* a, const unsigned* b) {
    asm volatile("mma.sync.aligned.m16n8k16.row.col.f32.bf16.bf16.f32 "
        "{%0,%1,%2,%3}, {%4,%5,%6,%7}, {%8,%9}, {%0,%1,%2,%3};"
        : "+f"(d[0]), "+f"(d[1]), "+f"(d[2]), "+f"(d[3])
        : "r"(a[0]), "r"(a[1]), "r"(a[2]), "r"(a[3]), "r"(b[0]), "r"(b[1]));
}
__device__ __forceinline__ void cp16(void* dst, const void* src) {
    unsigned d32 = (unsigned)__cvta_generic_to_shared(dst);
    asm volatile("cp.async.cg.shared.global [%0], [%1], 16;" :: "r"(d32), "l"(src));
}
__device__ __forceinline__ void cp_commit() { asm volatile("cp.async.commit_group;"); }
__device__ __forceinline__ void cp_wait1() { asm volatile("cp.async.wait_group 1;"); }
__device__ __forceinline__ void cp_wait0() { asm volatile("cp.async.wait_group 0;"); }

// ---------------- decorator ----------------
__global__ __launch_bounds__(256) void decorate_kernel(
    const float* __restrict__ c_ctx, const float* __restrict__ c_tgt,
    const float* __restrict__ y_ctx, const float* __restrict__ expo_ctx,
    const float* __restrict__ W1, const float* __restrict__ b1,
    const float* __restrict__ W2, const float* __restrict__ b2,
    const float* __restrict__ logk, float* __restrict__ c)
{
    const int row = blockIdx.x;
    const int j = threadIdx.x;
    if (row >= NC) {
        c[row * D + j] = c_tgt[(row - NC) * D + j];
        return;
    }
    __shared__ float t[D];
    const float y = y_ctx[row];
    t[j] = tanhf(y * W1[j] + b1[j]);
    __syncthreads();

    float acc = b2[j];
    #pragma unroll 8
    for (int d = 0; d < D; d++)
        acc += t[d] * W2[d * D + j];

    const float lk = logk[0];
    const float kappa = (lk > 20.f) ? lk : log1pf(expf(lk));
    const float e = expo_ctx[row];
    const float w = e / (e + kappa);
    c[row * D + j] = c_ctx[row * D + j] + w * acc;
}

// ---------------- tf32 GEMM, 64x64 tile, 128 thr, double-buffered cp.async ---
#define GBM 64
#define GBN 64
#define GBK 32
__device__ __forceinline__ void gemm_body(
    const float* __restrict__ A, const float* __restrict__ B,
    const float* __restrict__ bias, float* __restrict__ C,
    int N, int K, int relu)
{
    __shared__ float As[2][GBM][44];   // [m][k], pad 44 (16B-aligned rows, bank-clean)
    __shared__ float Bs[2][GBK][72];   // [k][n], pad 72

    const int tid = threadIdx.x;
    const int lane = tid & 31, warp = tid >> 5;
    const int wm = warp >> 1, wn = warp & 1;
    const int bm = blockIdx.y * GBM, bn = blockIdx.x * GBN;
    const int lq = lane >> 2, lr = lane & 3;

    float acc[2][4][4] = {};
    const int T = K / GBK;

    auto load_tile = [&](int t, int s) {
        const int k0 = t * GBK;
        #pragma unroll
        for (int r = 0; r < 4; r++) {               // A: 512 16B-chunks
            const int ch = tid + r * 128;
            const int row = ch >> 3, off = (ch & 7) * 4;
            cp16(&As[s][row][off], &A[(bm + row) * K + k0 + off]);
        }
        #pragma unroll
        for (int r = 0; r < 4; r++) {               // B: 512 16B-chunks
            const int ch = tid + r * 128;
            const int row = ch >> 4, off = (ch & 15) * 4;
            cp16(&Bs[s][row][off], &B[(k0 + row) * N + bn + off]);
        }
    };

    load_tile(0, 0); cp_commit();
    for (int t = 0; t < T; t++) {
        const int s = t & 1;
        if (t + 1 < T) { load_tile(t + 1, s ^ 1); cp_commit(); cp_wait1(); }
        else           { cp_wait0(); }
        __syncthreads();

        #pragma unroll
        for (int kz = 0; kz < GBK; kz += 8) {
            unsigned af[2][4], bf[4][2];
            #pragma unroll
            for (int mt = 0; mt < 2; mt++) {
                const int mr = wm * 32 + mt * 16 + lq;
                af[mt][0] = f2tf32(As[s][mr][kz + lr]);
                af[mt][1] = f2tf32(As[s][mr + 8][kz + lr]);
                af[mt][2] = f2tf32(As[s][mr][kz + lr + 4]);
                af[mt][3] = f2tf32(As[s][mr + 8][kz + lr + 4]);
            }
            #pragma unroll
            for (int nt = 0; nt < 4; nt++) {
                const int nc0 = wn * 32 + nt * 8 + lq;
                bf[nt][0] = f2tf32(Bs[s][kz + lr][nc0]);
                bf[nt][1] = f2tf32(Bs[s][kz + lr + 4][nc0]);
            }
            #pragma unroll
            for (int mt = 0; mt < 2; mt++)
                #pragma unroll
                for (int nt = 0; nt < 4; nt++)
                    mma_tf32(acc[mt][nt], af[mt], bf[nt]);
        }
        __syncthreads();
    }

    #pragma unroll
    for (int mt = 0; mt < 2; mt++) {
        const int row = bm + wm * 32 + mt * 16 + lq;
        #pragma unroll
        for (int nt = 0; nt < 4; nt++) {
            const int col = bn + wn * 32 + nt * 8 + lr * 2;
            const float b0 = bias[col], b1 = bias[col + 1];
            float v0 = acc[mt][nt][0] + b0, v1 = acc[mt][nt][1] + b1;
            float v2 = acc[mt][nt][2] + b0, v3 = acc[mt][nt][3] + b1;
            if (relu) {
                v0 = fmaxf(v0, 0.f); v1 = fmaxf(v1, 0.f);
                v2 = fmaxf(v2, 0.f); v3 = fmaxf(v3, 0.f);
            }
            *(float2*)&C[row * N + col] = make_float2(v0, v1);
            *(float2*)&C[(row + 8) * N + col] = make_float2(v2, v3);
        }
    }
}

__global__ __launch_bounds__(128) void gemm_tf32_kernel(
    const float* __restrict__ A, const float* __restrict__ B,
    const float* __restrict__ bias, float* __restrict__ C,
    int N, int K, int relu)
{
    gemm_body(A, B, bias, C, N, K, relu);
}

__global__ __launch_bounds__(128) void gemm_qkv_kernel(
    const float* __restrict__ A,
    const float* __restrict__ WQ, const float* __restrict__ bQ, float* __restrict__ Q,
    const float* __restrict__ WK, const float* __restrict__ bK, float* __restrict__ K_,
    const float* __restrict__ WV, const float* __restrict__ bV, float* __restrict__ V)
{
    const float* B; const float* bias; float* C;
    if (blockIdx.z == 0)      { B = WQ; bias = bQ; C = Q;  }
    else if (blockIdx.z == 1) { B = WK; bias = bK; C = K_; }
    else                      { B = WV; bias = bV; C = V;  }
    gemm_body(A, B, bias, C, D, D, 0);
}

// ---------------- K -> bf16, V -> bf16 transposed [d][token] -----------------
__global__ __launch_bounds__(256) void convert_kv_kernel(
    const float* __restrict__ K, const float* __restrict__ V,
    __nv_bfloat16* __restrict__ Kb, __nv_bfloat16* __restrict__ Vt)
{
    if (blockIdx.y == 0) {
        const int i = (blockIdx.x * 256 + threadIdx.x) * 4;   // NTOK*D/4 elems
        float4 v = *(const float4*)&K[i];
        *(__nv_bfloat162*)&Kb[i]     = __floats2bfloat162_rn(v.x, v.y);
        *(__nv_bfloat162*)&Kb[i + 2] = __floats2bfloat162_rn(v.z, v.w);
    } else {
        __shared__ float ts[32][33];
        const int tok0 = (blockIdx.x & 127) * 32;
        const int d0 = (blockIdx.x >> 7) * 32;
        const int c = threadIdx.x & 31, r8 = threadIdx.x >> 5;   // 32 x 8
        #pragma unroll
        for (int rr = 0; rr < 32; rr += 8)
            ts[r8 + rr][c] = V[(tok0 + r8 + rr) * D + d0 + c];
        __syncthreads();
        #pragma unroll
        for (int rr = 0; rr < 32; rr += 8)
            Vt[(d0 + r8 + rr) * NTOK + tok0 + c] = __float2bfloat16(ts[c][r8 + rr]);
    }
}

// ---------------- bf16 flash attention, double-buffered cp.async -------------
#define AQ 64
#define AK 64
__global__ __launch_bounds__(128) void attn_mma_kernel(
    const float* __restrict__ Qg, const __nv_bfloat16* __restrict__ Kb,
    const __nv_bfloat16* __restrict__ Vt,
    const float* __restrict__ Kg, const float* __restrict__ Vg,
    float* __restrict__ Og)
{
    __shared__ __nv_bfloat16 Ks[2][AK][40];    // [key][d]
    __shared__ __nv_bfloat16 Vts[2][HD][72];   // [d][key]

    const int hc = blockIdx.y * HD;
    const int qb = blockIdx.x * AQ;
    const int tid = threadIdx.x, lane = tid & 31, warp = tid >> 5;
    const int lq = lane >> 2, lr = lane & 3;
    const int qw = qb + warp * 16;
    const bool tgt = (qb >= NC);
    const int ntiles = tgt ? (NC / AK) : (NTOK / AK);
    const float scale = 0.17677669529663687f;

    auto load_kv = [&](int kt, int s) {
        const int kr = kt * AK;
        #pragma unroll
        for (int r = 0; r < 2; r++) {          // K: 256 chunks (64 rows x 4)
            const int ch = tid + r * 128;
            const int row = ch >> 2, off = (ch & 3) * 8;
            cp16(&Ks[s][row][off], &Kb[(kr + row) * D + hc + off]);
        }
        #pragma unroll
        for (int r = 0; r < 2; r++) {          // Vt: 256 chunks (32 rows x 8)
            const int ch = tid + r * 128;
            const int row = ch >> 3, off = (ch & 7) * 8;
            cp16(&Vts[s][row][off], &Vt[(hc + row) * NTOK + kr + off]);
        }
    };

    // Q fragments
    unsigned qa[2][4];
    {
        const int r0 = qw + lq;
        #pragma unroll
        for (int kc = 0; kc < 2; kc++) {
            const int d = hc + kc * 16 + lr * 2;
            float2 v00 = *(const float2*)&Qg[r0 * D + d];
            float2 v10 = *(const float2*)&Qg[(r0 + 8) * D + d];
            float2 v01 = *(const float2*)&Qg[r0 * D + d + 8];
            float2 v11 = *(const float2*)&Qg[(r0 + 8) * D + d + 8];
            qa[kc][0] = pack_bf16(v00.x, v00.y);
            qa[kc][1] = pack_bf16(v10.x, v10.y);
            qa[kc][2] = pack_bf16(v01.x, v01.y);
            qa[kc][3] = pack_bf16(v11.x, v11.y);
        }
    }

    float o[4][4] = {};
    float mrow[2] = { -INFINITY, -INFINITY };
    float lrow[2] = { 0.f, 0.f };

    load_kv(0, 0); cp_commit();
    for (int kt = 0; kt < ntiles; kt++) {
        const int s = kt & 1;
        if (kt + 1 < ntiles) { load_kv(kt + 1, s ^ 1); cp_commit(); cp_wait1(); }
        else                 { cp_wait0(); }
        __syncthreads();

        // S = Q @ K^T
        float sc[8][4] = {};
        #pragma unroll
        for (int nt = 0; nt < 8; nt++) {
            #pragma unroll
            for (int kc = 0; kc < 2; kc++) {
                unsigned bfr[2];
                bfr[0] = *(const unsigned*)&Ks[s][nt * 8 + lq][kc * 16 + lr * 2];
                bfr[1] = *(const unsigned*)&Ks[s][nt * 8 + lq][kc * 16 + lr * 2 + 8];
                mma_bf16(sc[nt], qa[kc], bfr);
            }
        }

        // online softmax
        float mt0 = -INFINITY, mt1 = -INFINITY;
        #pragma unroll
        for (int nt = 0; nt < 8; nt++) {
            sc[nt][0] *= scale; sc[nt][1] *= scale;
            sc[nt][2] *= scale; sc[nt][3] *= scale;
            mt0 = fmaxf(mt0, fmaxf(sc[nt][0], sc[nt][1]));
            mt1 = fmaxf(mt1, fmaxf(sc[nt][2], sc[nt][3]));
        }
        mt0 = fmaxf(mt0, __shfl_xor_sync(0xffffffffu, mt0, 1));
        mt0 = fmaxf(mt0, __shfl_xor_sync(0xffffffffu, mt0, 2));
        mt1 = fmaxf(mt1, __shfl_xor_sync(0xffffffffu, mt1, 1));
        mt1 = fmaxf(mt1, __shfl_xor_sync(0xffffffffu, mt1, 2));

        const float mn0 = fmaxf(mrow[0], mt0), mn1 = fmaxf(mrow[1], mt1);
        const float cr0 = __expf(mrow[0] - mn0), cr1 = __expf(mrow[1] - mn1);
        float rs0 = 0.f, rs1 = 0.f;
        #pragma unroll
        for (int nt = 0; nt < 8; nt++) {
            sc[nt][0] = __expf(sc[nt][0] - mn0);
            sc[nt][1] = __expf(sc[nt][1] - mn0);
            sc[nt][2] = __expf(sc[nt][2] - mn1);
            sc[nt][3] = __expf(sc[nt][3] - mn1);
            rs0 += sc[nt][0] + sc[nt][1];
            rs1 += sc[nt][2] + sc[nt][3];
        }
        rs0 += __shfl_xor_sync(0xffffffffu, rs0, 1);
        rs0 += __shfl_xor_sync(0xffffffffu, rs0, 2);
        rs1 += __shfl_xor_sync(0xffffffffu, rs1, 1);
        rs1 += __shfl_xor_sync(0xffffffffu, rs1, 2);
        lrow[0] = lrow[0] * cr0 + rs0;
        lrow[1] = lrow[1] * cr1 + rs1;
        mrow[0] = mn0; mrow[1] = mn1;
        #pragma unroll
        for (int nt = 0; nt < 4; nt++) {
            o[nt][0] *= cr0; o[nt][1] *= cr0;
            o[nt][2] *= cr1; o[nt][3] *= cr1;
        }

        // O += P @ V
        #pragma unroll
        for (int kc = 0; kc < 4; kc++) {
            unsigned pa[4];
            pa[0] = pack_bf16(sc[2 * kc][0],     sc[2 * kc][1]);
            pa[1] = pack_bf16(sc[2 * kc][2],     sc[2 * kc][3]);
            pa[2] = pack_bf16(sc[2 * kc + 1][0], sc[2 * kc + 1][1]);
            pa[3] = pack_bf16(sc[2 * kc + 1][2], sc[2 * kc + 1][3]);
            #pragma unroll
            for (int nt = 0; nt < 4; nt++) {
                unsigned bfr[2];
                bfr[0] = *(const unsigned*)&Vts[s][nt * 8 + lq][kc * 16 + lr * 2];
                bfr[1] = *(const unsigned*)&Vts[s][nt * 8 + lq][kc * 16 + lr * 2 + 8];
                mma_bf16(o[nt], pa, bfr);
            }
        }
        __syncthreads();
    }

    if (tgt) {   // fp32 self term
        #pragma unroll
        for (int rr = 0; rr < 2; rr++) {
            const int q = qw + lq + rr * 8;
            float sv = 0.f;
            #pragma unroll
            for (int d = 0; d < HD; d++)
                sv += Qg[q * D + hc + d] * Kg[q * D + hc + d];
            sv *= scale;
            const float mn = fmaxf(mrow[rr], sv);
            const float corr = __expf(mrow[rr] - mn);
            const float p = __expf(sv - mn);
            #pragma unroll
            for (int nt = 0; nt < 4; nt++) {
                const int dcol = hc + nt * 8 + lr * 2;
                o[nt][rr * 2 + 0] = o[nt][rr * 2 + 0] * corr + p * Vg[q * D + dcol];
                o[nt][rr * 2 + 1] = o[nt][rr * 2 + 1] * corr + p * Vg[q * D + dcol + 1];
            }
            lrow[rr] = lrow[rr] * corr + p;
            mrow[rr] = mn;
        }
    }

    const float inv0 = 1.f / lrow[0], inv1 = 1.f / lrow[1];
    const int r0 = qw + lq;
    #pragma unroll
    for (int nt = 0; nt < 4; nt++) {
        const int dcol = hc + nt * 8 + lr * 2;
        *(float2*)&Og[r0 * D + dcol] = make_float2(o[nt][0] * inv0, o[nt][1] * inv0);
        *(float2*)&Og[(r0 + 8) * D + dcol] = make_float2(o[nt][2] * inv1, o[nt][3] * inv1);
    }
}

// ---------------- fused residual add + LayerNorm ---------------------------
__global__ __launch_bounds__(256) void add_ln_kernel(
    float* __restrict__ c, const float* __restrict__ t,
    const float* __restrict__ g, const float* __restrict__ b)
{
    const int row = blockIdx.x;
    const int j = threadIdx.x;
    const int lane = j & 31, warp = j >> 5;
    __shared__ float wsum[8], wsq[8];
    __shared__ float s_mean, s_rstd;

    float x = c[row * D + j] + t[row * D + j];

    float s1 = x, s2 = x * x;
    #pragma unroll
    for (int o = 16; o > 0; o >>= 1) {
        s1 += __shfl_xor_sync(0xffffffffu, s1, o);
        s2 += __shfl_xor_sync(0xffffffffu, s2, o);
    }
    if (lane == 0) { wsum[warp] = s1; wsq[warp] = s2; }
    __syncthreads();
    if (warp == 0) {
        float v1 = (lane < 8) ? wsum[lane] : 0.f;
        float v2 = (lane < 8) ? wsq[lane] : 0.f;
        #pragma unroll
        for (int o = 4; o > 0; o >>= 1) {
            v1 += __shfl_xor_sync(0xffffffffu, v1, o);
            v2 += __shfl_xor_sync(0xffffffffu, v2, o);
        }
        if (lane == 0) {
            const float mean = v1 * (1.0f / D);
            float var = v2 * (1.0f / D) - mean * mean;
            var = fmaxf(var, 0.f);
            s_mean = mean;
            s_rstd = rsqrtf(var + 1e-5f);
        }
    }
    __syncthreads();
    c[row * D + j] = (x - s_mean) * s_rstd * g[j] + b[j];
}

// ---------------- output head ----------------------------------------------
__global__ __launch_bounds__(256) void out_kernel(
    const float* __restrict__ c, const float* __restrict__ W,
    const float* __restrict__ ob, const float* __restrict__ expo,
    float* __restrict__ out)
{
    const int i = blockIdx.x;
    const int j = threadIdx.x;
    const int lane = j & 31, warp = j >> 5;
    __shared__ float wred[8];
    float s = c[(NC + i) * D + j] * W[j];
    #pragma unroll
    for (int o = 16; o > 0; o >>= 1) s += __shfl_xor_sync(0xffffffffu, s, o);
    if (lane == 0) wred[warp] = s;
    __syncthreads();
    if (j == 0) {
        float v = wred[0];
        #pragma unroll
        for (int w = 1; w < 8; w++) v += wred[w];
        out[i] = expf(v + ob[0]) * expo[i];
    }
}

// ---------------- launch ----------------
extern "C" void kernel_launch(void* const* d_in, const int* in_sizes, int n_in,
                              void* d_out, int out_size)
{
    const float* c_ctx    = (const float*)d_in[0];
    const float* c_tgt    = (const float*)d_in[1];
    const float* y_ctx    = (const float*)d_in[2];
    const float* expo_ctx = (const float*)d_in[3];
    const float* expo_tgt = (const float*)d_in[4];
    const float* dec_W1   = (const float*)d_in[5];
    const float* dec_b1   = (const float*)d_in[6];
    const float* dec_W2   = (const float*)d_in[7];
    const float* dec_b2   = (const float*)d_in[8];
    const float* log_k    = (const float*)d_in[9];
    const float* WQ       = (const float*)d_in[10];
    const float* bQ       = (const float*)d_in[11];
    const float* WK       = (const float*)d_in[12];
    const float* bK       = (const float*)d_in[13];
    const float* WV       = (const float*)d_in[14];
    const float* bV       = (const float*)d_in[15];
    const float* WO       = (const float*)d_in[16];
    const float* bO       = (const float*)d_in[17];
    const float* ln1_g    = (const float*)d_in[18];
    const float* ln1_b    = (const float*)d_in[19];
    const float* ln2_g    = (const float*)d_in[20];
    const float* ln2_b    = (const float*)d_in[21];
    const float* ffn_W1   = (const float*)d_in[22];
    const float* ffn_b1   = (const float*)d_in[23];
    const float* ffn_W2   = (const float*)d_in[24];
    const float* ffn_b2   = (const float*)d_in[25];
    const float* out_W    = (const float*)d_in[26];
    const float* out_b    = (const float*)d_in[27];
    float* out = (float*)d_out;

    float *pc, *pq, *pk, *pv, *po, *pt;
    __nv_bfloat16 *pkb, *pvt;
    cudaGetSymbolAddress((void**)&pc, g_c);
    cudaGetSymbolAddress((void**)&pq, g_q);
    cudaGetSymbolAddress((void**)&pk, g_k);
    cudaGetSymbolAddress((void**)&pv, g_v);
    cudaGetSymbolAddress((void**)&po, g_o);
    cudaGetSymbolAddress((void**)&pt, g_t);
    cudaGetSymbolAddress((void**)&pkb, g_kb);
    cudaGetSymbolAddress((void**)&pvt, g_vt);

    decorate_kernel<<<NTOK, 256>>>(c_ctx, c_tgt, y_ctx, expo_ctx,
                                   dec_W1, dec_b1, dec_W2, dec_b2, log_k, pc);

    const dim3 gD(D / GBN, NTOK / GBM);          // 4 x 64
    const dim3 gQKV(D / GBN, NTOK / GBM, 3);     // 4 x 64 x 3
    const dim3 gFF1(FF / GBN, NTOK / GBM);       // 16 x 64
    const dim3 gCvt(1024, 2);
    const dim3 gAttn(NTOK / AQ, H);              // 64 x 8

    for (int l = 0; l < L; l++) {
        gemm_qkv_kernel<<<gQKV, 128>>>(pc,
            WQ + l * D * D, bQ + l * D, pq,
            WK + l * D * D, bK + l * D, pk,
            WV + l * D * D, bV + l * D, pv);

        convert_kv_kernel<<<gCvt, 256>>>(pk, pv, pkb, pvt);

        attn_mma_kernel<<<gAttn, 128>>>(pq, pkb, pvt, pk, pv, po);

        gemm_tf32_kernel<<<gD, 128>>>(po, WO + l * D * D, bO + l * D, pt, D, D, 0);
        add_ln_kernel<<<NTOK, 256>>>(pc, pt, ln1_g + l * D, ln1_b + l * D);

        gemm_tf32_kernel<<<gFF1, 128>>>(pc, ffn_W1 + l * D * FF, ffn_b1 + l * FF,
                                        pt, FF, D, 1);
        gemm_tf32_kernel<<<gD, 128>>>(pt, ffn_W2 + l * FF * D, ffn_b2 + l * D,
                                      po, D, FF, 0);
        add_ln_kernel<<<NTOK, 256>>>(pc, po, ln2_g + l * D, ln2_b + l * D);
    }

    out_kernel<<<NT, 256>>>(pc, out_W, out_b, expo_tgt, out);
}

// round 6
// speedup vs baseline: 6.7266x; 1.1077x over previous
#include <cuda_runtime.h>
#include <cuda_bf16.h>
#include <math.h>

#define NC 3072
#define NT 1024
#define NTOK 4096
#define D 256
#define H 8
#define HD 32
#define FF 1024
#define L 2

// ---------------- scratch ----------------
__device__ float g_c[NTOK * D];
__device__ float g_q[NTOK * D];
__device__ float g_k[NTOK * D];
__device__ float g_v[NTOK * D];
__device__ float g_o[NTOK * D];
__device__ float g_t[NTOK * FF];
__device__ __nv_bfloat16 g_kb[NTOK * D];   // bf16 K
__device__ __nv_bfloat16 g_vt[D * NTOK];   // bf16 V^T  [d][token]

// ---------------- helpers ----------------
__device__ __forceinline__ unsigned f2tf32(float x) {
    unsigned r; asm("cvt.rna.tf32.f32 %0, %1;" : "=r"(r) : "f"(x)); return r;
}
__device__ __forceinline__ unsigned pack_bf16(float x, float y) {
    __nv_bfloat162 h = __floats2bfloat162_rn(x, y);
    return *(unsigned*)&h;
}
__device__ __forceinline__ float fexp2(float x) {
    float r; asm("ex2.approx.ftz.f32 %0, %1;" : "=f"(r) : "f"(x)); return r;
}
__device__ __forceinline__ void mma_tf32(float* d, const unsigned* a, const unsigned* b) {
    asm volatile("mma.sync.aligned.m16n8k8.row.col.f32.tf32.tf32.f32 "
        "{%0,%1,%2,%3}, {%4,%5,%6,%7}, {%8,%9}, {%0,%1,%2,%3};"
        : "+f"(d[0]), "+f"(d[1]), "+f"(d[2]), "+f"(d[3])
        : "r"(a[0]), "r"(a[1]), "r"(a[2]), "r"(a[3]), "r"(b[0]), "r"(b[1]));
}
__device__ __forceinline__ void mma_bf16(float* d, const unsigned* a, const unsigned* b) {
    asm volatile("mma.sync.aligned.m16n8k16.row.col.f32.bf16.bf16.f32 "
        "{%0,%1,%2,%3}, {%4,%5,%6,%7}, {%8,%9}, {%0,%1,%2,%3};"
        : "+f"(d[0]), "+f"(d[1]), "+f"(d[2]), "+f"(d[3])
        : "r"(a[0]), "r"(a[1]), "r"(a[2]), "r"(a[3]), "r"(b[0]), "r"(b[1]));
}
__device__ __forceinline__ void ldsm_x4(unsigned* r, unsigned addr) {
    asm volatile("ldmatrix.sync.aligned.m8n8.x4.shared.b16 {%0,%1,%2,%3}, [%4];"
        : "=r"(r[0]), "=r"(r[1]), "=r"(r[2]), "=r"(r[3]) : "r"(addr));
}
__device__ __forceinline__ void cp16(void* dst, const void* src) {
    unsigned d32 = (unsigned)__cvta_generic_to_shared(dst);
    asm volatile("cp.async.cg.shared.global [%0], [%1], 16;" :: "r"(d32), "l"(src));
}
__device__ __forceinline__ void cp_commit() { asm volatile("cp.async.commit_group;"); }
__device__ __forceinline__ void cp_wait1() { asm volatile("cp.async.wait_group 1;"); }
__device__ __forceinline__ void cp_wait0() { asm volatile("cp.async.wait_group 0;"); }

// ---------------- decorator ----------------
__global__ __launch_bounds__(256) void decorate_kernel(
    const float* __restrict__ c_ctx, const float* __restrict__ c_tgt,
    const float* __restrict__ y_ctx, const float* __restrict__ expo_ctx,
    const float* __restrict__ W1, const float* __restrict__ b1,
    const float* __restrict__ W2, const float* __restrict__ b2,
    const float* __restrict__ logk, float* __restrict__ c)
{
    const int row = blockIdx.x;
    const int j = threadIdx.x;
    if (row >= NC) {
        c[row * D + j] = c_tgt[(row - NC) * D + j];
        return;
    }
    __shared__ float t[D];
    const float y = y_ctx[row];
    t[j] = tanhf(y * W1[j] + b1[j]);
    __syncthreads();

    float acc = b2[j];
    #pragma unroll 8
    for (int d = 0; d < D; d++)
        acc += t[d] * W2[d * D + j];

    const float lk = logk[0];
    const float kappa = (lk > 20.f) ? lk : log1pf(expf(lk));
    const float e = expo_ctx[row];
    const float w = e / (e + kappa);
    c[row * D + j] = c_ctx[row * D + j] + w * acc;
}

// ---------------- tf32 GEMM, 64x64 tile, 128 thr, double-buffered cp.async ---
#define GBM 64
#define GBN 64
#define GBK 32
__device__ __forceinline__ void gemm_body(
    const float* __restrict__ A, const float* __restrict__ B,
    const float* __restrict__ bias, float* __restrict__ C,
    int N, int K, int relu)
{
    __shared__ float As[2][GBM][44];
    __shared__ float Bs[2][GBK][72];

    const int tid = threadIdx.x;
    const int lane = tid & 31, warp = tid >> 5;
    const int wm = warp >> 1, wn = warp & 1;
    const int bm = blockIdx.y * GBM, bn = blockIdx.x * GBN;
    const int lq = lane >> 2, lr = lane & 3;

    float acc[2][4][4] = {};
    const int T = K / GBK;

    auto load_tile = [&](int t, int s) {
        const int k0 = t * GBK;
        #pragma unroll
        for (int r = 0; r < 4; r++) {
            const int ch = tid + r * 128;
            const int row = ch >> 3, off = (ch & 7) * 4;
            cp16(&As[s][row][off], &A[(bm + row) * K + k0 + off]);
        }
        #pragma unroll
        for (int r = 0; r < 4; r++) {
            const int ch = tid + r * 128;
            const int row = ch >> 4, off = (ch & 15) * 4;
            cp16(&Bs[s][row][off], &B[(k0 + row) * N + bn + off]);
        }
    };

    load_tile(0, 0); cp_commit();
    for (int t = 0; t < T; t++) {
        const int s = t & 1;
        if (t + 1 < T) { load_tile(t + 1, s ^ 1); cp_commit(); cp_wait1(); }
        else           { cp_wait0(); }
        __syncthreads();

        #pragma unroll
        for (int kz = 0; kz < GBK; kz += 8) {
            unsigned af[2][4], bf[4][2];
            #pragma unroll
            for (int mt = 0; mt < 2; mt++) {
                const int mr = wm * 32 + mt * 16 + lq;
                af[mt][0] = f2tf32(As[s][mr][kz + lr]);
                af[mt][1] = f2tf32(As[s][mr + 8][kz + lr]);
                af[mt][2] = f2tf32(As[s][mr][kz + lr + 4]);
                af[mt][3] = f2tf32(As[s][mr + 8][kz + lr + 4]);
            }
            #pragma unroll
            for (int nt = 0; nt < 4; nt++) {
                const int nc0 = wn * 32 + nt * 8 + lq;
                bf[nt][0] = f2tf32(Bs[s][kz + lr][nc0]);
                bf[nt][1] = f2tf32(Bs[s][kz + lr + 4][nc0]);
            }
            #pragma unroll
            for (int mt = 0; mt < 2; mt++)
                #pragma unroll
                for (int nt = 0; nt < 4; nt++)
                    mma_tf32(acc[mt][nt], af[mt], bf[nt]);
        }
        __syncthreads();
    }

    #pragma unroll
    for (int mt = 0; mt < 2; mt++) {
        const int row = bm + wm * 32 + mt * 16 + lq;
        #pragma unroll
        for (int nt = 0; nt < 4; nt++) {
            const int col = bn + wn * 32 + nt * 8 + lr * 2;
            const float b0 = bias[col], b1 = bias[col + 1];
            float v0 = acc[mt][nt][0] + b0, v1 = acc[mt][nt][1] + b1;
            float v2 = acc[mt][nt][2] + b0, v3 = acc[mt][nt][3] + b1;
            if (relu) {
                v0 = fmaxf(v0, 0.f); v1 = fmaxf(v1, 0.f);
                v2 = fmaxf(v2, 0.f); v3 = fmaxf(v3, 0.f);
            }
            *(float2*)&C[row * N + col] = make_float2(v0, v1);
            *(float2*)&C[(row + 8) * N + col] = make_float2(v2, v3);
        }
    }
}

__global__ __launch_bounds__(128) void gemm_tf32_kernel(
    const float* __restrict__ A, const float* __restrict__ B,
    const float* __restrict__ bias, float* __restrict__ C,
    int N, int K, int relu)
{
    gemm_body(A, B, bias, C, N, K, relu);
}

__global__ __launch_bounds__(128) void gemm_qkv_kernel(
    const float* __restrict__ A,
    const float* __restrict__ WQ, const float* __restrict__ bQ, float* __restrict__ Q,
    const float* __restrict__ WK, const float* __restrict__ bK, float* __restrict__ K_,
    const float* __restrict__ WV, const float* __restrict__ bV, float* __restrict__ V)
{
    const float* B; const float* bias; float* C;
    if (blockIdx.z == 0)      { B = WQ; bias = bQ; C = Q;  }
    else if (blockIdx.z == 1) { B = WK; bias = bK; C = K_; }
    else                      { B = WV; bias = bV; C = V;  }
    gemm_body(A, B, bias, C, D, D, 0);
}

// ---------------- K -> bf16, V -> bf16 transposed [d][token] -----------------
__global__ __launch_bounds__(256) void convert_kv_kernel(
    const float* __restrict__ K, const float* __restrict__ V,
    __nv_bfloat16* __restrict__ Kb, __nv_bfloat16* __restrict__ Vt)
{
    if (blockIdx.y == 0) {
        const int i = (blockIdx.x * 256 + threadIdx.x) * 4;
        float4 v = *(const float4*)&K[i];
        *(__nv_bfloat162*)&Kb[i]     = __floats2bfloat162_rn(v.x, v.y);
        *(__nv_bfloat162*)&Kb[i + 2] = __floats2bfloat162_rn(v.z, v.w);
    } else {
        __shared__ float ts[32][33];
        const int tok0 = (blockIdx.x & 127) * 32;
        const int d0 = (blockIdx.x >> 7) * 32;
        const int c = threadIdx.x & 31, r8 = threadIdx.x >> 5;
        #pragma unroll
        for (int rr = 0; rr < 32; rr += 8)
            ts[r8 + rr][c] = V[(tok0 + r8 + rr) * D + d0 + c];
        __syncthreads();
        #pragma unroll
        for (int rr = 0; rr < 32; rr += 8)
            Vt[(d0 + r8 + rr) * NTOK + tok0 + c] = __float2bfloat16(ts[c][r8 + rr]);
    }
}

// ---------------- bf16 flash attention: exp2 softmax + ldmatrix --------------
// Q fragments pre-scaled by scale*log2(e): mma output is directly in log2 domain.
#define AQ 64
#define AK 64
__global__ __launch_bounds__(128, 4) void attn_mma_kernel(
    const float* __restrict__ Qg, const __nv_bfloat16* __restrict__ Kb,
    const __nv_bfloat16* __restrict__ Vt,
    const float* __restrict__ Kg, const float* __restrict__ Vg,
    float* __restrict__ Og)
{
    __shared__ __nv_bfloat16 Ks[2][AK][40];    // [key][d], row stride 80B (bank-clean)
    __shared__ __nv_bfloat16 Vts[2][HD][72];   // [d][key], row stride 144B (bank-clean)

    const int hc = blockIdx.y * HD;
    const int qb = blockIdx.x * AQ;
    const int tid = threadIdx.x, lane = tid & 31, warp = tid >> 5;
    const int lq = lane >> 2, lr = lane & 3;
    const int qw = qb + warp * 16;
    const bool tgt = (qb >= NC);
    const int ntiles = tgt ? (NC / AK) : (NTOK / AK);
    const float scale2 = 0.17677669529663687f * 1.4426950408889634f;  // /sqrt(32)*log2e

    // ldmatrix per-thread base offsets
    const unsigned ks_addr0 = (unsigned)__cvta_generic_to_shared(&Ks[0][0][0])
                            + ((lane & 7) * 40 + (lane >> 3) * 8) * 2;
    const unsigned vt_addr0 = (unsigned)__cvta_generic_to_shared(&Vts[0][0][0])
                            + ((lane & 7) * 72 + (lane >> 3) * 8) * 2;
    const unsigned ks_stride = AK * 40 * 2;    // bytes per buffer
    const unsigned vt_stride = HD * 72 * 2;

    auto load_kv = [&](int kt, int s) {
        const int kr = kt * AK;
        #pragma unroll
        for (int r = 0; r < 2; r++) {
            const int ch = tid + r * 128;
            const int row = ch >> 2, off = (ch & 3) * 8;
            cp16(&Ks[s][row][off], &Kb[(kr + row) * D + hc + off]);
        }
        #pragma unroll
        for (int r = 0; r < 2; r++) {
            const int ch = tid + r * 128;
            const int row = ch >> 3, off = (ch & 7) * 8;
            cp16(&Vts[s][row][off], &Vt[(hc + row) * NTOK + kr + off]);
        }
    };

    // Q fragments, pre-scaled into log2 domain
    unsigned qa[2][4];
    {
        const int r0 = qw + lq;
        #pragma unroll
        for (int kc = 0; kc < 2; kc++) {
            const int d = hc + kc * 16 + lr * 2;
            float2 v00 = *(const float2*)&Qg[r0 * D + d];
            float2 v10 = *(const float2*)&Qg[(r0 + 8) * D + d];
            float2 v01 = *(const float2*)&Qg[r0 * D + d + 8];
            float2 v11 = *(const float2*)&Qg[(r0 + 8) * D + d + 8];
            qa[kc][0] = pack_bf16(v00.x * scale2, v00.y * scale2);
            qa[kc][1] = pack_bf16(v10.x * scale2, v10.y * scale2);
            qa[kc][2] = pack_bf16(v01.x * scale2, v01.y * scale2);
            qa[kc][3] = pack_bf16(v11.x * scale2, v11.y * scale2);
        }
    }

    float o[4][4] = {};
    float mrow[2] = { -INFINITY, -INFINITY };
    float lrow[2] = { 0.f, 0.f };

    load_kv(0, 0); cp_commit();
    for (int kt = 0; kt < ntiles; kt++) {
        const int s = kt & 1;
        if (kt + 1 < ntiles) { load_kv(kt + 1, s ^ 1); cp_commit(); cp_wait1(); }
        else                 { cp_wait0(); }
        __syncthreads();

        const unsigned kbase = ks_addr0 + s * ks_stride;
        const unsigned vbase = vt_addr0 + s * vt_stride;

        // S = Q @ K^T (already scaled, log2 domain)
        float sc[8][4] = {};
        #pragma unroll
        for (int nt = 0; nt < 8; nt++) {
            unsigned kb[4];
            ldsm_x4(kb, kbase + nt * 640);          // 8 keys x 32 d (2 k-chunks)
            mma_bf16(sc[nt], qa[0], kb);
            mma_bf16(sc[nt], qa[1], kb + 2);
        }

        // online softmax (exp2 domain)
        float mt0 = -INFINITY, mt1 = -INFINITY;
        #pragma unroll
        for (int nt = 0; nt < 8; nt++) {
            mt0 = fmaxf(mt0, fmaxf(sc[nt][0], sc[nt][1]));
            mt1 = fmaxf(mt1, fmaxf(sc[nt][2], sc[nt][3]));
        }
        mt0 = fmaxf(mt0, __shfl_xor_sync(0xffffffffu, mt0, 1));
        mt0 = fmaxf(mt0, __shfl_xor_sync(0xffffffffu, mt0, 2));
        mt1 = fmaxf(mt1, __shfl_xor_sync(0xffffffffu, mt1, 1));
        mt1 = fmaxf(mt1, __shfl_xor_sync(0xffffffffu, mt1, 2));

        const float mn0 = fmaxf(mrow[0], mt0), mn1 = fmaxf(mrow[1], mt1);
        const float cr0 = fexp2(mrow[0] - mn0), cr1 = fexp2(mrow[1] - mn1);
        float rs0 = 0.f, rs1 = 0.f;
        #pragma unroll
        for (int nt = 0; nt < 8; nt++) {
            sc[nt][0] = fexp2(sc[nt][0] - mn0);
            sc[nt][1] = fexp2(sc[nt][1] - mn0);
            sc[nt][2] = fexp2(sc[nt][2] - mn1);
            sc[nt][3] = fexp2(sc[nt][3] - mn1);
            rs0 += sc[nt][0] + sc[nt][1];
            rs1 += sc[nt][2] + sc[nt][3];
        }
        rs0 += __shfl_xor_sync(0xffffffffu, rs0, 1);
        rs0 += __shfl_xor_sync(0xffffffffu, rs0, 2);
        rs1 += __shfl_xor_sync(0xffffffffu, rs1, 1);
        rs1 += __shfl_xor_sync(0xffffffffu, rs1, 2);
        lrow[0] = lrow[0] * cr0 + rs0;
        lrow[1] = lrow[1] * cr1 + rs1;
        mrow[0] = mn0; mrow[1] = mn1;
        #pragma unroll
        for (int nt = 0; nt < 4; nt++) {
            o[nt][0] *= cr0; o[nt][1] *= cr0;
            o[nt][2] *= cr1; o[nt][3] *= cr1;
        }

        // pack P fragments
        unsigned pa[4][4];
        #pragma unroll
        for (int kc = 0; kc < 4; kc++) {
            pa[kc][0] = pack_bf16(sc[2 * kc][0],     sc[2 * kc][1]);
            pa[kc][1] = pack_bf16(sc[2 * kc][2],     sc[2 * kc][3]);
            pa[kc][2] = pack_bf16(sc[2 * kc + 1][0], sc[2 * kc + 1][1]);
            pa[kc][3] = pack_bf16(sc[2 * kc + 1][2], sc[2 * kc + 1][3]);
        }

        // O += P @ V
        #pragma unroll
        for (int nt = 0; nt < 4; nt++) {
            unsigned vb[8];
            ldsm_x4(vb,     vbase + nt * 1152);        // keys 0..31
            ldsm_x4(vb + 4, vbase + nt * 1152 + 64);   // keys 32..63
            mma_bf16(o[nt], pa[0], vb + 0);
            mma_bf16(o[nt], pa[1], vb + 2);
            mma_bf16(o[nt], pa[2], vb + 4);
            mma_bf16(o[nt], pa[3], vb + 6);
        }
        __syncthreads();
    }

    if (tgt) {   // fp32 self term (log2 domain)
        #pragma unroll
        for (int rr = 0; rr < 2; rr++) {
            const int q = qw + lq + rr * 8;
            float sv = 0.f;
            #pragma unroll
            for (int d = 0; d < HD; d++)
                sv += Qg[q * D + hc + d] * Kg[q * D + hc + d];
            sv *= scale2;
            const float mn = fmaxf(mrow[rr], sv);
            const float corr = fexp2(mrow[rr] - mn);
            const float p = fexp2(sv - mn);
            #pragma unroll
            for (int nt = 0; nt < 4; nt++) {
                const int dcol = hc + nt * 8 + lr * 2;
                o[nt][rr * 2 + 0] = o[nt][rr * 2 + 0] * corr + p * Vg[q * D + dcol];
                o[nt][rr * 2 + 1] = o[nt][rr * 2 + 1] * corr + p * Vg[q * D + dcol + 1];
            }
            lrow[rr] = lrow[rr] * corr + p;
            mrow[rr] = mn;
        }
    }

    const float inv0 = 1.f / lrow[0], inv1 = 1.f / lrow[1];
    const int r0 = qw + lq;
    #pragma unroll
    for (int nt = 0; nt < 4; nt++) {
        const int dcol = hc + nt * 8 + lr * 2;
        *(float2*)&Og[r0 * D + dcol] = make_float2(o[nt][0] * inv0, o[nt][1] * inv0);
        *(float2*)&Og[(r0 + 8) * D + dcol] = make_float2(o[nt][2] * inv1, o[nt][3] * inv1);
    }
}

// ---------------- fused residual add + LayerNorm ---------------------------
__global__ __launch_bounds__(256) void add_ln_kernel(
    float* __restrict__ c, const float* __restrict__ t,
    const float* __restrict__ g, const float* __restrict__ b)
{
    const int row = blockIdx.x;
    const int j = threadIdx.x;
    const int lane = j & 31, warp = j >> 5;
    __shared__ float wsum[8], wsq[8];
    __shared__ float s_mean, s_rstd;

    float x = c[row * D + j] + t[row * D + j];

    float s1 = x, s2 = x * x;
    #pragma unroll
    for (int o = 16; o > 0; o >>= 1) {
        s1 += __shfl_xor_sync(0xffffffffu, s1, o);
        s2 += __shfl_xor_sync(0xffffffffu, s2, o);
    }
    if (lane == 0) { wsum[warp] = s1; wsq[warp] = s2; }
    __syncthreads();
    if (warp == 0) {
        float v1 = (lane < 8) ? wsum[lane] : 0.f;
        float v2 = (lane < 8) ? wsq[lane] : 0.f;
        #pragma unroll
        for (int o = 4; o > 0; o >>= 1) {
            v1 += __shfl_xor_sync(0xffffffffu, v1, o);
            v2 += __shfl_xor_sync(0xffffffffu, v2, o);
        }
        if (lane == 0) {
            const float mean = v1 * (1.0f / D);
            float var = v2 * (1.0f / D) - mean * mean;
            var = fmaxf(var, 0.f);
            s_mean = mean;
            s_rstd = rsqrtf(var + 1e-5f);
        }
    }
    __syncthreads();
    c[row * D + j] = (x - s_mean) * s_rstd * g[j] + b[j];
}

// ---------------- output head ----------------------------------------------
__global__ __launch_bounds__(256) void out_kernel(
    const float* __restrict__ c, const float* __restrict__ W,
    const float* __restrict__ ob, const float* __restrict__ expo,
    float* __restrict__ out)
{
    const int i = blockIdx.x;
    const int j = threadIdx.x;
    const int lane = j & 31, warp = j >> 5;
    __shared__ float wred[8];
    float s = c[(NC + i) * D + j] * W[j];
    #pragma unroll
    for (int o = 16; o > 0; o >>= 1) s += __shfl_xor_sync(0xffffffffu, s, o);
    if (lane == 0) wred[warp] = s;
    __syncthreads();
    if (j == 0) {
        float v = wred[0];
        #pragma unroll
        for (int w = 1; w < 8; w++) v += wred[w];
        out[i] = expf(v + ob[0]) * expo[i];
    }
}

// ---------------- launch ----------------
extern "C" void kernel_launch(void* const* d_in, const int* in_sizes, int n_in,
                              void* d_out, int out_size)
{
    const float* c_ctx    = (const float*)d_in[0];
    const float* c_tgt    = (const float*)d_in[1];
    const float* y_ctx    = (const float*)d_in[2];
    const float* expo_ctx = (const float*)d_in[3];
    const float* expo_tgt = (const float*)d_in[4];
    const float* dec_W1   = (const float*)d_in[5];
    const float* dec_b1   = (const float*)d_in[6];
    const float* dec_W2   = (const float*)d_in[7];
    const float* dec_b2   = (const float*)d_in[8];
    const float* log_k    = (const float*)d_in[9];
    const float* WQ       = (const float*)d_in[10];
    const float* bQ       = (const float*)d_in[11];
    const float* WK       = (const float*)d_in[12];
    const float* bK       = (const float*)d_in[13];
    const float* WV       = (const float*)d_in[14];
    const float* bV       = (const float*)d_in[15];
    const float* WO       = (const float*)d_in[16];
    const float* bO       = (const float*)d_in[17];
    const float* ln1_g    = (const float*)d_in[18];
    const float* ln1_b    = (const float*)d_in[19];
    const float* ln2_g    = (const float*)d_in[20];
    const float* ln2_b    = (const float*)d_in[21];
    const float* ffn_W1   = (const float*)d_in[22];
    const float* ffn_b1   = (const float*)d_in[23];
    const float* ffn_W2   = (const float*)d_in[24];
    const float* ffn_b2   = (const float*)d_in[25];
    const float* out_W    = (const float*)d_in[26];
    const float* out_b    = (const float*)d_in[27];
    float* out = (float*)d_out;

    float *pc, *pq, *pk, *pv, *po, *pt;
    __nv_bfloat16 *pkb, *pvt;
    cudaGetSymbolAddress((void**)&pc, g_c);
    cudaGetSymbolAddress((void**)&pq, g_q);
    cudaGetSymbolAddress((void**)&pk, g_k);
    cudaGetSymbolAddress((void**)&pv, g_v);
    cudaGetSymbolAddress((void**)&po, g_o);
    cudaGetSymbolAddress((void**)&pt, g_t);
    cudaGetSymbolAddress((void**)&pkb, g_kb);
    cudaGetSymbolAddress((void**)&pvt, g_vt);

    decorate_kernel<<<NTOK, 256>>>(c_ctx, c_tgt, y_ctx, expo_ctx,
                                   dec_W1, dec_b1, dec_W2, dec_b2, log_k, pc);

    const dim3 gD(D / GBN, NTOK / GBM);          // 4 x 64
    const dim3 gQKV(D / GBN, NTOK / GBM, 3);     // 4 x 64 x 3
    const dim3 gFF1(FF / GBN, NTOK / GBM);       // 16 x 64
    const dim3 gCvt(1024, 2);
    const dim3 gAttn(NTOK / AQ, H);              // 64 x 8

    for (int l = 0; l < L; l++) {
        gemm_qkv_kernel<<<gQKV, 128>>>(pc,
            WQ + l * D * D, bQ + l * D, pq,
            WK + l * D * D, bK + l * D, pk,
            WV + l * D * D, bV + l * D, pv);

        convert_kv_kernel<<<gCvt, 256>>>(pk, pv, pkb, pvt);

        attn_mma_kernel<<<gAttn, 128>>>(pq, pkb, pvt, pk, pv, po);

        gemm_tf32_kernel<<<gD, 128>>>(po, WO + l * D * D, bO + l * D, pt, D, D, 0);
        add_ln_kernel<<<NTOK, 256>>>(pc, pt, ln1_g + l * D, ln1_b + l * D);

        gemm_tf32_kernel<<<gFF1, 128>>>(pc, ffn_W1 + l * D * FF, ffn_b1 + l * FF,
                                        pt, FF, D, 1);
        gemm_tf32_kernel<<<gD, 128>>>(pt, ffn_W2 + l * FF * D, ffn_b2 + l * D,
                                      po, D, FF, 0);
        add_ln_kernel<<<NTOK, 256>>>(pc, po, ln2_g + l * D, ln2_b + l * D);
    }

    out_kernel<<<NT, 256>>>(pc, out_W, out_b, expo_tgt, out);
}